// round 6
// baseline (speedup 1.0000x reference)
#include <cuda_runtime.h>
#include <cuda_bf16.h>

// Scratch (allocation-free rule: __device__ globals).
#define MAX_N 131072
__device__ float g_diag[MAX_N];   // sigmoid(x@w + b) per node
__device__ float g_deg[MAX_N];    // in-degree -> later its reciprocal
__device__ int   g_is64;          // 1 if edge_index is int64, 0 if int32

// ---------------------------------------------------------------------------
// Kernel 0: dtype probe. Reads up to 16 leading entries as int64; all in
// [0,N) is essentially impossible for reinterpreted int32 pairs (P ~ 1e-80).
// ---------------------------------------------------------------------------
__global__ void probe_kernel(const void* __restrict__ ei, int N, int E) {
    const long long* p = (const long long*)ei;
    int cnt = E < 16 ? E : 16;     // 2E int32 words always cover cnt int64s
    int ok = 1;
    for (int i = 0; i < cnt; ++i) {
        long long v = p[i];
        if (v < 0 || v >= (long long)N) ok = 0;
    }
    g_is64 = ok;
}

// ---------------------------------------------------------------------------
// Kernel 1: warp-per-row dot product  diag[i] = sigmoid(x[i]·w + b)
// Also zeroes g_deg[i] (saves a separate memset launch).
// ---------------------------------------------------------------------------
__global__ void diag_kernel(const float* __restrict__ x,
                            const float* __restrict__ w,
                            const float* __restrict__ b,
                            int N, int D) {
    int warp = (blockIdx.x * blockDim.x + threadIdx.x) >> 5;
    int lane = threadIdx.x & 31;
    if (warp >= N) return;

    const float4* xr = (const float4*)(x + (size_t)warp * D);
    const float4* wv = (const float4*)w;
    int nvec = D >> 2;                 // float4s per row (64 for D=256)
    float s = 0.0f;
    #pragma unroll 2
    for (int i = lane; i < nvec; i += 32) {
        float4 a  = __ldg(&xr[i]);
        float4 ww = __ldg(&wv[i]);
        s += a.x * ww.x + a.y * ww.y + a.z * ww.z + a.w * ww.w;
    }
    #pragma unroll
    for (int o = 16; o; o >>= 1) s += __shfl_xor_sync(0xFFFFFFFFu, s, o);

    if (lane == 0) {
        float z = s + b[0];
        g_diag[warp] = 1.0f / (1.0f + __expf(-z));
        g_deg[warp]  = 0.0f;
    }
}

// ---------------------------------------------------------------------------
// Kernel 2: degree count over col.  Float adds of 1.0f are exact and
// order-independent for counts < 2^24 -> deterministic.
// 8 edges/thread, front-batched 128-bit loads. Uniform dtype branch.
// ---------------------------------------------------------------------------
__global__ void deg_kernel(const void* __restrict__ eiv, int E) {
    const int is64 = g_is64;             // single uniform read
    int e = (blockIdx.x * blockDim.x + threadIdx.x) * 8;
    if (is64) {
        const long long* col = (const long long*)eiv + E;   // second row
        if (e + 8 <= E) {
            longlong2 c0 = *(const longlong2*)(col + e);
            longlong2 c1 = *(const longlong2*)(col + e + 2);
            longlong2 c2 = *(const longlong2*)(col + e + 4);
            longlong2 c3 = *(const longlong2*)(col + e + 6);
            atomicAdd(&g_deg[(int)c0.x], 1.0f);
            atomicAdd(&g_deg[(int)c0.y], 1.0f);
            atomicAdd(&g_deg[(int)c1.x], 1.0f);
            atomicAdd(&g_deg[(int)c1.y], 1.0f);
            atomicAdd(&g_deg[(int)c2.x], 1.0f);
            atomicAdd(&g_deg[(int)c2.y], 1.0f);
            atomicAdd(&g_deg[(int)c3.x], 1.0f);
            atomicAdd(&g_deg[(int)c3.y], 1.0f);
        } else {
            for (; e < E; ++e) atomicAdd(&g_deg[(int)col[e]], 1.0f);
        }
    } else {
        const int* col = (const int*)eiv + E;
        if (e + 8 <= E) {
            int4 c0 = *(const int4*)(col + e);
            int4 c1 = *(const int4*)(col + e + 4);
            atomicAdd(&g_deg[c0.x], 1.0f);
            atomicAdd(&g_deg[c0.y], 1.0f);
            atomicAdd(&g_deg[c0.z], 1.0f);
            atomicAdd(&g_deg[c0.w], 1.0f);
            atomicAdd(&g_deg[c1.x], 1.0f);
            atomicAdd(&g_deg[c1.y], 1.0f);
            atomicAdd(&g_deg[c1.z], 1.0f);
            atomicAdd(&g_deg[c1.w], 1.0f);
        } else {
            for (; e < E; ++e) atomicAdd(&g_deg[col[e]], 1.0f);
        }
    }
}

// ---------------------------------------------------------------------------
// Kernel 3: invert degree once per node (keeps MUFU out of the E-sized loop).
// 1/0 -> inf matches torch deg.pow(-1). 4 nodes/thread, vectorized.
// ---------------------------------------------------------------------------
__global__ void inv_kernel(int N) {
    int i = (blockIdx.x * blockDim.x + threadIdx.x) * 4;
    if (i + 4 <= N) {
        float4 v = *(float4*)(g_deg + i);
        v.x = 1.0f / v.x; v.y = 1.0f / v.y;
        v.z = 1.0f / v.z; v.w = 1.0f / v.w;
        *(float4*)(g_deg + i) = v;
    } else {
        for (; i < N; ++i) g_deg[i] = 1.0f / g_deg[i];
    }
}

// ---------------------------------------------------------------------------
// Kernel 4: val[e] = deg_inv[row[e]] * attr[e] * diag[col[e]]
// 8 edges/thread, front-batched loads; gather tables (400 KB each) L2-resident.
// Uniform dtype branch.
// ---------------------------------------------------------------------------
__global__ void val_kernel(const void* __restrict__ eiv,
                           const float* __restrict__ attr,
                           float* __restrict__ out, int E) {
    const int is64 = g_is64;             // single uniform read
    int e = (blockIdx.x * blockDim.x + threadIdx.x) * 8;
    if (is64) {
        const long long* row = (const long long*)eiv;
        const long long* col = row + E;
        if (e + 8 <= E) {
            longlong2 r0 = *(const longlong2*)(row + e);
            longlong2 r1 = *(const longlong2*)(row + e + 2);
            longlong2 r2 = *(const longlong2*)(row + e + 4);
            longlong2 r3 = *(const longlong2*)(row + e + 6);
            longlong2 c0 = *(const longlong2*)(col + e);
            longlong2 c1 = *(const longlong2*)(col + e + 2);
            longlong2 c2 = *(const longlong2*)(col + e + 4);
            longlong2 c3 = *(const longlong2*)(col + e + 6);
            float4 a0 = *(const float4*)(attr + e);
            float4 a1 = *(const float4*)(attr + e + 4);
            float4 v0, v1;
            v0.x = g_deg[(int)r0.x] * a0.x * g_diag[(int)c0.x];
            v0.y = g_deg[(int)r0.y] * a0.y * g_diag[(int)c0.y];
            v0.z = g_deg[(int)r1.x] * a0.z * g_diag[(int)c1.x];
            v0.w = g_deg[(int)r1.y] * a0.w * g_diag[(int)c1.y];
            v1.x = g_deg[(int)r2.x] * a1.x * g_diag[(int)c2.x];
            v1.y = g_deg[(int)r2.y] * a1.y * g_diag[(int)c2.y];
            v1.z = g_deg[(int)r3.x] * a1.z * g_diag[(int)c3.x];
            v1.w = g_deg[(int)r3.y] * a1.w * g_diag[(int)c3.y];
            *(float4*)(out + e)     = v0;
            *(float4*)(out + e + 4) = v1;
        } else {
            for (; e < E; ++e)
                out[e] = g_deg[(int)row[e]] * attr[e] * g_diag[(int)col[e]];
        }
    } else {
        const int* row = (const int*)eiv;
        const int* col = row + E;
        if (e + 8 <= E) {
            int4 r0 = *(const int4*)(row + e);
            int4 r1 = *(const int4*)(row + e + 4);
            int4 c0 = *(const int4*)(col + e);
            int4 c1 = *(const int4*)(col + e + 4);
            float4 a0 = *(const float4*)(attr + e);
            float4 a1 = *(const float4*)(attr + e + 4);
            float4 v0, v1;
            v0.x = g_deg[r0.x] * a0.x * g_diag[c0.x];
            v0.y = g_deg[r0.y] * a0.y * g_diag[c0.y];
            v0.z = g_deg[r0.z] * a0.z * g_diag[c0.z];
            v0.w = g_deg[r0.w] * a0.w * g_diag[c0.w];
            v1.x = g_deg[r1.x] * a1.x * g_diag[c1.x];
            v1.y = g_deg[r1.y] * a1.y * g_diag[c1.y];
            v1.z = g_deg[r1.z] * a1.z * g_diag[c1.z];
            v1.w = g_deg[r1.w] * a1.w * g_diag[c1.w];
            *(float4*)(out + e)     = v0;
            *(float4*)(out + e + 4) = v1;
        } else {
            for (; e < E; ++e)
                out[e] = g_deg[row[e]] * attr[e] * g_diag[col[e]];
        }
    }
}

// Cast edge_index to float into out[0 .. 2E) for the flattened-tuple layout.
__global__ void idx_cast_kernel(const void* __restrict__ eiv,
                                float* __restrict__ out, int n2e) {
    const int is64 = g_is64;
    int i = (blockIdx.x * blockDim.x + threadIdx.x) * 4;
    if (is64) {
        const long long* ei = (const long long*)eiv;
        if (i + 4 <= n2e) {
            longlong2 a = *(const longlong2*)(ei + i);
            longlong2 b = *(const longlong2*)(ei + i + 2);
            *(float4*)(out + i) =
                make_float4((float)a.x, (float)a.y, (float)b.x, (float)b.y);
        } else {
            for (; i < n2e; ++i) out[i] = (float)ei[i];
        }
    } else {
        const int* ei = (const int*)eiv;
        if (i + 4 <= n2e) {
            int4 a = *(const int4*)(ei + i);
            *(float4*)(out + i) =
                make_float4((float)a.x, (float)a.y, (float)a.z, (float)a.w);
        } else {
            for (; i < n2e; ++i) out[i] = (float)ei[i];
        }
    }
}

// Raw copy of edge_index (indices-only output layout), width-preserving.
__global__ void idx_copy_kernel(const void* __restrict__ src,
                                void* __restrict__ dst, int n2e) {
    const int is64 = g_is64;
    int i = (blockIdx.x * blockDim.x + threadIdx.x) * 4;
    if (is64) {
        const long long* s = (const long long*)src;
        long long* d = (long long*)dst;
        if (i + 4 <= n2e) {
            *(longlong2*)(d + i)     = *(const longlong2*)(s + i);
            *(longlong2*)(d + i + 2) = *(const longlong2*)(s + i + 2);
        } else {
            for (; i < n2e; ++i) d[i] = s[i];
        }
    } else {
        const int* s = (const int*)src;
        int* d = (int*)dst;
        if (i + 4 <= n2e) {
            *(int4*)(d + i) = *(const int4*)(s + i);
        } else {
            for (; i < n2e; ++i) d[i] = s[i];
        }
    }
}

extern "C" void kernel_launch(void* const* d_in, const int* in_sizes, int n_in,
                              void* d_out, int out_size) {
    const float* x    = (const float*)d_in[0];
    const void*  ei   = d_in[1];                 // [2, E] int32 or int64
    const float* attr = (const float*)d_in[2];
    const float* w    = (const float*)d_in[3];
    const float* b    = (const float*)d_in[4];

    int D = in_sizes[3];
    int N = in_sizes[0] / D;
    int E = in_sizes[2];

    // Stage 0: dtype probe (1 thread)
    probe_kernel<<<1, 1>>>(ei, N, E);

    // Stage 1: diag + deg reset (warp per row)
    {
        int threads = 256;
        int warpsPerBlock = threads / 32;
        int blocks = (N + warpsPerBlock - 1) / warpsPerBlock;
        diag_kernel<<<blocks, threads>>>(x, w, b, N, D);
    }
    // Stage 2: degree
    {
        int threads = 512;
        int work = (E + 7) / 8;
        int blocks = (work + threads - 1) / threads;
        deg_kernel<<<blocks, threads>>>(ei, E);
    }
    // Stage 3: invert
    {
        int threads = 256;
        int work = (N + 3) / 4;
        int blocks = (work + threads - 1) / threads;
        inv_kernel<<<blocks, threads>>>(N);
    }
    // Stage 4: values (+ optional index handling depending on out_size)
    float* val_out = (float*)d_out;
    if (out_size == 3 * E) {
        // flattened (edge_index cast to float, then values)
        int n2e = 2 * E;
        int threads = 256;
        int work = (n2e + 3) / 4;
        int blocks = (work + threads - 1) / threads;
        idx_cast_kernel<<<blocks, threads>>>(ei, (float*)d_out, n2e);
        val_out = (float*)d_out + n2e;
    } else if (out_size == 2 * E) {
        // indices only (raw width-preserving copy)
        int n2e = 2 * E;
        int threads = 256;
        int work = (n2e + 3) / 4;
        int blocks = (work + threads - 1) / threads;
        idx_copy_kernel<<<blocks, threads>>>(ei, d_out, n2e);
        return;
    }
    {
        int threads = 512;
        int work = (E + 7) / 8;
        int blocks = (work + threads - 1) / threads;
        val_kernel<<<blocks, threads>>>(ei, attr, val_out, E);
    }
}

// round 10
// speedup vs baseline: 1.2026x; 1.2026x over previous
#include <cuda_runtime.h>
#include <cuda_bf16.h>

// Scratch (allocation-free rule: __device__ globals, zero-initialized at load).
#define MAX_N 131072
__device__ float g_diag[MAX_N];   // sigmoid(x@w + b) per node
__device__ float g_deg[MAX_N];    // INVARIANT: all-zero at kernel_launch entry;
                                  // deg accumulates, inv_kernel rezeroes.
__device__ float g_dinv[MAX_N];   // 1/deg
__device__ int   g_is64;          // only used by the rare hedge output paths

// ---------------------------------------------------------------------------
// Per-CTA dtype self-probe: read up to 16 leading entries as int64; all in
// [0,N) is essentially impossible for reinterpreted int32 pairs (P ~ 1e-80).
// Called by ONE thread per CTA; loads are L2-broadcast hits after CTA 0.
// ---------------------------------------------------------------------------
__device__ __forceinline__ int probe_is64_once(const void* __restrict__ ei,
                                               long long N, int E) {
    const long long* p = (const long long*)ei;
    int cnt = E < 16 ? (E < 1 ? 1 : E) : 16;
    int ok = 1;
    for (int i = 0; i < cnt; ++i) {
        long long v = __ldg(p + i);
        if (v < 0 || v >= N) ok = 0;
    }
    return ok;
}

// ---------------------------------------------------------------------------
// Kernel 1 (FUSED): diag CTAs + deg CTAs interleaved in one grid.
//  - deg CTAs (bid % f == 0): histogram col into g_deg via float atomics
//    (exact & order-independent for counts < 2^24 -> deterministic).
//    g_deg is zero at entry by the zero-at-exit invariant.
//  - diag CTAs (others): warp-per-row  diag[i] = sigmoid(x[i]·w + b).
// Interleave co-schedules DRAM-streaming (diag) with L2-atomic (deg) work.
// ---------------------------------------------------------------------------
__global__ void __launch_bounds__(256)
fused_diag_deg(const float* __restrict__ x,
               const float* __restrict__ w,
               const float* __restrict__ bb,
               const void* __restrict__ eiv,
               int N, int D, int E,
               int nDiag, int nDeg, int f) {
    __shared__ int s_is64;
    int bid = blockIdx.x;
    int tid = threadIdx.x;

    if (bid % f == 0) {
        // ---- degree CTA ----
        int degIdx = bid / f;
        if (degIdx >= nDeg) return;
        if (tid == 0) s_is64 = probe_is64_once(eiv, N, E);
        __syncthreads();
        const int is64 = s_is64;
        int e = (degIdx * blockDim.x + tid) * 8;
        if (is64) {
            const long long* col = (const long long*)eiv + E;   // second row
            if (e + 8 <= E) {
                longlong2 c0 = __ldcs((const longlong2*)(col + e));
                longlong2 c1 = __ldcs((const longlong2*)(col + e + 2));
                longlong2 c2 = __ldcs((const longlong2*)(col + e + 4));
                longlong2 c3 = __ldcs((const longlong2*)(col + e + 6));
                atomicAdd(&g_deg[(int)c0.x], 1.0f);
                atomicAdd(&g_deg[(int)c0.y], 1.0f);
                atomicAdd(&g_deg[(int)c1.x], 1.0f);
                atomicAdd(&g_deg[(int)c1.y], 1.0f);
                atomicAdd(&g_deg[(int)c2.x], 1.0f);
                atomicAdd(&g_deg[(int)c2.y], 1.0f);
                atomicAdd(&g_deg[(int)c3.x], 1.0f);
                atomicAdd(&g_deg[(int)c3.y], 1.0f);
            } else {
                for (; e < E; ++e) atomicAdd(&g_deg[(int)col[e]], 1.0f);
            }
        } else {
            const int* col = (const int*)eiv + E;
            if (e + 8 <= E) {
                int4 c0 = __ldcs((const int4*)(col + e));
                int4 c1 = __ldcs((const int4*)(col + e + 4));
                atomicAdd(&g_deg[c0.x], 1.0f);
                atomicAdd(&g_deg[c0.y], 1.0f);
                atomicAdd(&g_deg[c0.z], 1.0f);
                atomicAdd(&g_deg[c0.w], 1.0f);
                atomicAdd(&g_deg[c1.x], 1.0f);
                atomicAdd(&g_deg[c1.y], 1.0f);
                atomicAdd(&g_deg[c1.z], 1.0f);
                atomicAdd(&g_deg[c1.w], 1.0f);
            } else {
                for (; e < E; ++e) atomicAdd(&g_deg[col[e]], 1.0f);
            }
        }
    } else {
        // ---- diag CTA: warp-per-row dot product ----
        int diagIdx = bid - bid / f - 1;
        if (diagIdx >= nDiag) return;
        int warpInBlk = tid >> 5;
        int lane = tid & 31;
        int row = diagIdx * (blockDim.x >> 5) + warpInBlk;
        if (row >= N) return;

        const float4* xr = (const float4*)(x + (size_t)row * D);
        const float4* wv = (const float4*)w;
        int nvec = D >> 2;               // float4s per row (64 for D=256)
        float s = 0.0f;
        #pragma unroll 2
        for (int i = lane; i < nvec; i += 32) {
            float4 a  = __ldcs(&xr[i]);   // streaming: don't pollute L2
            float4 ww = wv[i];            // tiny, reused: default caching
            s += a.x * ww.x + a.y * ww.y + a.z * ww.z + a.w * ww.w;
        }
        #pragma unroll
        for (int o = 16; o; o >>= 1) s += __shfl_xor_sync(0xFFFFFFFFu, s, o);

        if (lane == 0) {
            float z = s + bb[0];
            g_diag[row] = 1.0f / (1.0f + __expf(-z));
        }
    }
}

// ---------------------------------------------------------------------------
// Kernel 2: g_dinv = 1/g_deg, and REZERO g_deg (restores the zero-at-entry
// invariant for the next graph replay). 1/0 -> inf matches torch deg.pow(-1).
// ---------------------------------------------------------------------------
__global__ void __launch_bounds__(256) inv_kernel(int N) {
    int i = (blockIdx.x * blockDim.x + threadIdx.x) * 4;
    if (i + 4 <= N) {
        float4 v = *(float4*)(g_deg + i);
        float4 r;
        r.x = 1.0f / v.x; r.y = 1.0f / v.y;
        r.z = 1.0f / v.z; r.w = 1.0f / v.w;
        *(float4*)(g_dinv + i) = r;
        *(float4*)(g_deg + i)  = make_float4(0.f, 0.f, 0.f, 0.f);
    } else {
        for (; i < N; ++i) {
            g_dinv[i] = 1.0f / g_deg[i];
            g_deg[i]  = 0.0f;
        }
    }
}

// ---------------------------------------------------------------------------
// Kernel 3: val[e] = g_dinv[row[e]] * attr[e] * g_diag[col[e]]
// 8 edges/thread, front-batched loads; streams use __ldcs/__stcs so the
// 1.2 MB gather tables stay L2-resident. Per-CTA dtype self-probe.
// ---------------------------------------------------------------------------
__global__ void __launch_bounds__(256)
val_kernel(const void* __restrict__ eiv,
           const float* __restrict__ attr,
           float* __restrict__ out, int N, int E) {
    __shared__ int s_is64;
    int tid = threadIdx.x;
    if (tid == 0) s_is64 = probe_is64_once(eiv, N, E);
    __syncthreads();
    const int is64 = s_is64;

    int e = (blockIdx.x * blockDim.x + tid) * 8;
    if (is64) {
        const long long* row = (const long long*)eiv;
        const long long* col = row + E;
        if (e + 8 <= E) {
            longlong2 r0 = __ldcs((const longlong2*)(row + e));
            longlong2 r1 = __ldcs((const longlong2*)(row + e + 2));
            longlong2 r2 = __ldcs((const longlong2*)(row + e + 4));
            longlong2 r3 = __ldcs((const longlong2*)(row + e + 6));
            longlong2 c0 = __ldcs((const longlong2*)(col + e));
            longlong2 c1 = __ldcs((const longlong2*)(col + e + 2));
            longlong2 c2 = __ldcs((const longlong2*)(col + e + 4));
            longlong2 c3 = __ldcs((const longlong2*)(col + e + 6));
            float4 a0 = __ldcs((const float4*)(attr + e));
            float4 a1 = __ldcs((const float4*)(attr + e + 4));
            float4 v0, v1;
            v0.x = g_dinv[(int)r0.x] * a0.x * g_diag[(int)c0.x];
            v0.y = g_dinv[(int)r0.y] * a0.y * g_diag[(int)c0.y];
            v0.z = g_dinv[(int)r1.x] * a0.z * g_diag[(int)c1.x];
            v0.w = g_dinv[(int)r1.y] * a0.w * g_diag[(int)c1.y];
            v1.x = g_dinv[(int)r2.x] * a1.x * g_diag[(int)c2.x];
            v1.y = g_dinv[(int)r2.y] * a1.y * g_diag[(int)c2.y];
            v1.z = g_dinv[(int)r3.x] * a1.z * g_diag[(int)c3.x];
            v1.w = g_dinv[(int)r3.y] * a1.w * g_diag[(int)c3.y];
            __stcs((float4*)(out + e),     v0);
            __stcs((float4*)(out + e + 4), v1);
        } else {
            for (; e < E; ++e)
                out[e] = g_dinv[(int)row[e]] * attr[e] * g_diag[(int)col[e]];
        }
    } else {
        const int* row = (const int*)eiv;
        const int* col = row + E;
        if (e + 8 <= E) {
            int4 r0 = __ldcs((const int4*)(row + e));
            int4 r1 = __ldcs((const int4*)(row + e + 4));
            int4 c0 = __ldcs((const int4*)(col + e));
            int4 c1 = __ldcs((const int4*)(col + e + 4));
            float4 a0 = __ldcs((const float4*)(attr + e));
            float4 a1 = __ldcs((const float4*)(attr + e + 4));
            float4 v0, v1;
            v0.x = g_dinv[r0.x] * a0.x * g_diag[c0.x];
            v0.y = g_dinv[r0.y] * a0.y * g_diag[c0.y];
            v0.z = g_dinv[r0.z] * a0.z * g_diag[c0.z];
            v0.w = g_dinv[r0.w] * a0.w * g_diag[c0.w];
            v1.x = g_dinv[r1.x] * a1.x * g_diag[c1.x];
            v1.y = g_dinv[r1.y] * a1.y * g_diag[c1.y];
            v1.z = g_dinv[r1.z] * a1.z * g_diag[c1.z];
            v1.w = g_dinv[r1.w] * a1.w * g_diag[c1.w];
            __stcs((float4*)(out + e),     v0);
            __stcs((float4*)(out + e + 4), v1);
        } else {
            for (; e < E; ++e)
                out[e] = g_dinv[row[e]] * attr[e] * g_diag[col[e]];
        }
    }
}

// ---------------------------------------------------------------------------
// Hedge-path kernels (only launched for unexpected out_size layouts).
// ---------------------------------------------------------------------------
__global__ void probe_kernel(const void* __restrict__ ei, int N, int E) {
    g_is64 = probe_is64_once(ei, N, E);
}

__global__ void idx_cast_kernel(const void* __restrict__ eiv,
                                float* __restrict__ out, int n2e) {
    const int is64 = g_is64;
    int i = (blockIdx.x * blockDim.x + threadIdx.x) * 4;
    if (is64) {
        const long long* ei = (const long long*)eiv;
        if (i + 4 <= n2e) {
            longlong2 a = *(const longlong2*)(ei + i);
            longlong2 b = *(const longlong2*)(ei + i + 2);
            *(float4*)(out + i) =
                make_float4((float)a.x, (float)a.y, (float)b.x, (float)b.y);
        } else {
            for (; i < n2e; ++i) out[i] = (float)ei[i];
        }
    } else {
        const int* ei = (const int*)eiv;
        if (i + 4 <= n2e) {
            int4 a = *(const int4*)(ei + i);
            *(float4*)(out + i) =
                make_float4((float)a.x, (float)a.y, (float)a.z, (float)a.w);
        } else {
            for (; i < n2e; ++i) out[i] = (float)ei[i];
        }
    }
}

__global__ void idx_copy_kernel(const void* __restrict__ src,
                                void* __restrict__ dst, int n2e) {
    const int is64 = g_is64;
    int i = (blockIdx.x * blockDim.x + threadIdx.x) * 4;
    if (is64) {
        const long long* s = (const long long*)src;
        long long* d = (long long*)dst;
        if (i + 4 <= n2e) {
            *(longlong2*)(d + i)     = *(const longlong2*)(s + i);
            *(longlong2*)(d + i + 2) = *(const longlong2*)(s + i + 2);
        } else {
            for (; i < n2e; ++i) d[i] = s[i];
        }
    } else {
        const int* s = (const int*)src;
        int* d = (int*)dst;
        if (i + 4 <= n2e) {
            *(int4*)(d + i) = *(const int4*)(s + i);
        } else {
            for (; i < n2e; ++i) d[i] = s[i];
        }
    }
}

extern "C" void kernel_launch(void* const* d_in, const int* in_sizes, int n_in,
                              void* d_out, int out_size) {
    const float* x    = (const float*)d_in[0];
    const void*  ei   = d_in[1];                 // [2, E] int32 or int64
    const float* attr = (const float*)d_in[2];
    const float* w    = (const float*)d_in[3];
    const float* b    = (const float*)d_in[4];

    int D = in_sizes[3];
    int N = in_sizes[0] / D;
    int E = in_sizes[2];

    const int threads = 256;

    // Stage 1 (fused): diag + degree in one interleaved grid.
    {
        int warpsPerBlock = threads / 32;                  // 8 rows per CTA
        int nDiag = (N + warpsPerBlock - 1) / warpsPerBlock;
        int edgesPerCTA = threads * 8;
        int nDeg = (E + edgesPerCTA - 1) / edgesPerCTA;
        int total = nDiag + nDeg;
        int f = (total + nDeg - 1) / nDeg;                 // interleave stride
        int grid = total + f;                              // spares guarded
        fused_diag_deg<<<grid, threads>>>(x, w, b, ei, N, D, E,
                                          nDiag, nDeg, f);
    }
    // Stage 2: invert degree + rezero g_deg (restores invariant for replay).
    {
        int work = (N + 3) / 4;
        int blocks = (work + threads - 1) / threads;
        inv_kernel<<<blocks, threads>>>(N);
    }
    // Stage 3: values (+ hedge layouts).
    float* val_out = (float*)d_out;
    if (out_size == 3 * E) {
        probe_kernel<<<1, 1>>>(ei, N, E);
        int n2e = 2 * E;
        int work = (n2e + 3) / 4;
        int blocks = (work + threads - 1) / threads;
        idx_cast_kernel<<<blocks, threads>>>(ei, (float*)d_out, n2e);
        val_out = (float*)d_out + n2e;
    } else if (out_size == 2 * E) {
        probe_kernel<<<1, 1>>>(ei, N, E);
        int n2e = 2 * E;
        int work = (n2e + 3) / 4;
        int blocks = (work + threads - 1) / threads;
        idx_copy_kernel<<<blocks, threads>>>(ei, d_out, n2e);
        return;
    }
    {
        int work = (E + 7) / 8;
        int blocks = (work + threads - 1) / threads;
        val_kernel<<<blocks, threads>>>(ei, attr, val_out, N, E);
    }
}

// round 13
// speedup vs baseline: 1.2337x; 1.0259x over previous
#include <cuda_runtime.h>
#include <cuda_bf16.h>

// Scratch (allocation-free rule: __device__ globals, zero-initialized at load).
#define MAX_N 131072
__device__ float g_diag[MAX_N];   // sigmoid(x@w + b) per node
__device__ float g_deg[MAX_N];    // INVARIANT: all-zero at kernel_launch entry;
                                  // deg accumulates, inv_kernel rezeroes.
__device__ float g_dinv[MAX_N];   // 1/deg
__device__ int   g_is64;          // only used by the rare hedge output paths

// ---------------------------------------------------------------------------
// Per-CTA dtype self-probe: read up to 16 leading entries as int64; all in
// [0,N) is essentially impossible for reinterpreted int32 pairs (P ~ 1e-80).
// Called by ONE thread per CTA; loads are L2-broadcast hits after CTA 0.
// ---------------------------------------------------------------------------
__device__ __forceinline__ int probe_is64_once(const void* __restrict__ ei,
                                               long long N, int E) {
    const long long* p = (const long long*)ei;
    int cnt = E < 16 ? (E < 1 ? 1 : E) : 16;
    int ok = 1;
    for (int i = 0; i < cnt; ++i) {
        long long v = __ldg(p + i);
        if (v < 0 || v >= N) ok = 0;
    }
    return ok;
}

// ---------------------------------------------------------------------------
// Kernel 1 (3-WAY FUSED): deg + cast + diag CTA roles in one grid.
//  - deg CTAs  (bid % f == 0):      histogram col into g_deg (float atomics:
//        exact & order-independent for counts < 2^24 -> deterministic).
//  - cast CTAs (j % h == 0):        out[0..2E) = (float)edge_index  (only
//        when castOut != nullptr, i.e. the flattened-tuple output layout).
//  - diag CTAs (rest):              warp-per-row diag[i]=sigmoid(x[i]·w+b).
// Interleave co-schedules DRAM-streaming (diag, cast-write) with L2-atomic
// (deg) work; cast's ~51MB of traffic hides under diag's 102MB read stream.
// ---------------------------------------------------------------------------
__global__ void __launch_bounds__(256)
fused_diag_deg_cast(const float* __restrict__ x,
                    const float* __restrict__ w,
                    const float* __restrict__ bb,
                    const void* __restrict__ eiv,
                    float* __restrict__ castOut,
                    int N, int D, int E,
                    int nDiag, int nDeg, int nCast, int f, int h) {
    __shared__ int s_is64;
    int bid = blockIdx.x;
    int tid = threadIdx.x;

    if (bid % f == 0) {
        // ---- degree CTA ----
        int degIdx = bid / f;
        if (degIdx >= nDeg) return;
        if (tid == 0) s_is64 = probe_is64_once(eiv, N, E);
        __syncthreads();
        const int is64 = s_is64;
        int e = (degIdx * blockDim.x + tid) * 8;
        if (is64) {
            const long long* col = (const long long*)eiv + E;   // second row
            if (e + 8 <= E) {
                longlong2 c0 = __ldcs((const longlong2*)(col + e));
                longlong2 c1 = __ldcs((const longlong2*)(col + e + 2));
                longlong2 c2 = __ldcs((const longlong2*)(col + e + 4));
                longlong2 c3 = __ldcs((const longlong2*)(col + e + 6));
                atomicAdd(&g_deg[(int)c0.x], 1.0f);
                atomicAdd(&g_deg[(int)c0.y], 1.0f);
                atomicAdd(&g_deg[(int)c1.x], 1.0f);
                atomicAdd(&g_deg[(int)c1.y], 1.0f);
                atomicAdd(&g_deg[(int)c2.x], 1.0f);
                atomicAdd(&g_deg[(int)c2.y], 1.0f);
                atomicAdd(&g_deg[(int)c3.x], 1.0f);
                atomicAdd(&g_deg[(int)c3.y], 1.0f);
            } else {
                for (; e < E; ++e) atomicAdd(&g_deg[(int)col[e]], 1.0f);
            }
        } else {
            const int* col = (const int*)eiv + E;
            if (e + 8 <= E) {
                int4 c0 = __ldcs((const int4*)(col + e));
                int4 c1 = __ldcs((const int4*)(col + e + 4));
                atomicAdd(&g_deg[c0.x], 1.0f);
                atomicAdd(&g_deg[c0.y], 1.0f);
                atomicAdd(&g_deg[c0.z], 1.0f);
                atomicAdd(&g_deg[c0.w], 1.0f);
                atomicAdd(&g_deg[c1.x], 1.0f);
                atomicAdd(&g_deg[c1.y], 1.0f);
                atomicAdd(&g_deg[c1.z], 1.0f);
                atomicAdd(&g_deg[c1.w], 1.0f);
            } else {
                for (; e < E; ++e) atomicAdd(&g_deg[col[e]], 1.0f);
            }
        }
        return;
    }

    int j = bid - bid / f - 1;        // dense index among non-deg CTAs

    if (j % h == 0) {
        // ---- cast CTA: out[i] = (float)edge_index[i], 8 elems/thread ----
        int castIdx = j / h;
        if (castIdx >= nCast || castOut == nullptr) return;
        if (tid == 0) s_is64 = probe_is64_once(eiv, N, E);
        __syncthreads();
        const int is64 = s_is64;
        int n2e = 2 * E;
        int i = (castIdx * blockDim.x + tid) * 8;
        if (is64) {
            const long long* ei = (const long long*)eiv;
            if (i + 8 <= n2e) {
                longlong2 a0 = __ldcs((const longlong2*)(ei + i));
                longlong2 a1 = __ldcs((const longlong2*)(ei + i + 2));
                longlong2 a2 = __ldcs((const longlong2*)(ei + i + 4));
                longlong2 a3 = __ldcs((const longlong2*)(ei + i + 6));
                __stcs((float4*)(castOut + i),
                       make_float4((float)a0.x, (float)a0.y,
                                   (float)a1.x, (float)a1.y));
                __stcs((float4*)(castOut + i + 4),
                       make_float4((float)a2.x, (float)a2.y,
                                   (float)a3.x, (float)a3.y));
            } else {
                for (; i < n2e; ++i) castOut[i] = (float)ei[i];
            }
        } else {
            const int* ei = (const int*)eiv;
            if (i + 8 <= n2e) {
                int4 a0 = __ldcs((const int4*)(ei + i));
                int4 a1 = __ldcs((const int4*)(ei + i + 4));
                __stcs((float4*)(castOut + i),
                       make_float4((float)a0.x, (float)a0.y,
                                   (float)a0.z, (float)a0.w));
                __stcs((float4*)(castOut + i + 4),
                       make_float4((float)a1.x, (float)a1.y,
                                   (float)a1.z, (float)a1.w));
            } else {
                for (; i < n2e; ++i) castOut[i] = (float)ei[i];
            }
        }
        return;
    }

    // ---- diag CTA: warp-per-row dot product ----
    int diagIdx = j - j / h - 1;
    if (diagIdx >= nDiag) return;
    int warpInBlk = tid >> 5;
    int lane = tid & 31;
    int row = diagIdx * (blockDim.x >> 5) + warpInBlk;
    if (row >= N) return;

    const float4* xr = (const float4*)(x + (size_t)row * D);
    const float4* wv = (const float4*)w;
    int nvec = D >> 2;               // float4s per row (64 for D=256)
    float s = 0.0f;
    #pragma unroll 2
    for (int i = lane; i < nvec; i += 32) {
        float4 a  = __ldcs(&xr[i]);   // streaming: don't pollute L2
        float4 ww = wv[i];            // tiny, reused: default caching
        s += a.x * ww.x + a.y * ww.y + a.z * ww.z + a.w * ww.w;
    }
    #pragma unroll
    for (int o = 16; o; o >>= 1) s += __shfl_xor_sync(0xFFFFFFFFu, s, o);

    if (lane == 0) {
        float z = s + bb[0];
        g_diag[row] = 1.0f / (1.0f + __expf(-z));
    }
}

// ---------------------------------------------------------------------------
// Kernel 2: g_dinv = 1/g_deg, and REZERO g_deg (restores the zero-at-entry
// invariant for the next graph replay). 1/0 -> inf matches torch deg.pow(-1).
// ---------------------------------------------------------------------------
__global__ void __launch_bounds__(256) inv_kernel(int N) {
    int i = (blockIdx.x * blockDim.x + threadIdx.x) * 4;
    if (i + 4 <= N) {
        float4 v = *(float4*)(g_deg + i);
        float4 r;
        r.x = 1.0f / v.x; r.y = 1.0f / v.y;
        r.z = 1.0f / v.z; r.w = 1.0f / v.w;
        *(float4*)(g_dinv + i) = r;
        *(float4*)(g_deg + i)  = make_float4(0.f, 0.f, 0.f, 0.f);
    } else {
        for (; i < N; ++i) {
            g_dinv[i] = 1.0f / g_deg[i];
            g_deg[i]  = 0.0f;
        }
    }
}

// ---------------------------------------------------------------------------
// Kernel 3: val[e] = g_dinv[row[e]] * attr[e] * g_diag[col[e]]
// 8 edges/thread, front-batched loads; streams use __ldcs/__stcs so the
// 1.2 MB gather tables stay L2-resident. Per-CTA dtype self-probe.
// ---------------------------------------------------------------------------
__global__ void __launch_bounds__(256)
val_kernel(const void* __restrict__ eiv,
           const float* __restrict__ attr,
           float* __restrict__ out, int N, int E) {
    __shared__ int s_is64;
    int tid = threadIdx.x;
    if (tid == 0) s_is64 = probe_is64_once(eiv, N, E);
    __syncthreads();
    const int is64 = s_is64;

    int e = (blockIdx.x * blockDim.x + tid) * 8;
    if (is64) {
        const long long* row = (const long long*)eiv;
        const long long* col = row + E;
        if (e + 8 <= E) {
            longlong2 r0 = __ldcs((const longlong2*)(row + e));
            longlong2 r1 = __ldcs((const longlong2*)(row + e + 2));
            longlong2 r2 = __ldcs((const longlong2*)(row + e + 4));
            longlong2 r3 = __ldcs((const longlong2*)(row + e + 6));
            longlong2 c0 = __ldcs((const longlong2*)(col + e));
            longlong2 c1 = __ldcs((const longlong2*)(col + e + 2));
            longlong2 c2 = __ldcs((const longlong2*)(col + e + 4));
            longlong2 c3 = __ldcs((const longlong2*)(col + e + 6));
            float4 a0 = __ldcs((const float4*)(attr + e));
            float4 a1 = __ldcs((const float4*)(attr + e + 4));
            float4 v0, v1;
            v0.x = g_dinv[(int)r0.x] * a0.x * g_diag[(int)c0.x];
            v0.y = g_dinv[(int)r0.y] * a0.y * g_diag[(int)c0.y];
            v0.z = g_dinv[(int)r1.x] * a0.z * g_diag[(int)c1.x];
            v0.w = g_dinv[(int)r1.y] * a0.w * g_diag[(int)c1.y];
            v1.x = g_dinv[(int)r2.x] * a1.x * g_diag[(int)c2.x];
            v1.y = g_dinv[(int)r2.y] * a1.y * g_diag[(int)c2.y];
            v1.z = g_dinv[(int)r3.x] * a1.z * g_diag[(int)c3.x];
            v1.w = g_dinv[(int)r3.y] * a1.w * g_diag[(int)c3.y];
            __stcs((float4*)(out + e),     v0);
            __stcs((float4*)(out + e + 4), v1);
        } else {
            for (; e < E; ++e)
                out[e] = g_dinv[(int)row[e]] * attr[e] * g_diag[(int)col[e]];
        }
    } else {
        const int* row = (const int*)eiv;
        const int* col = row + E;
        if (e + 8 <= E) {
            int4 r0 = __ldcs((const int4*)(row + e));
            int4 r1 = __ldcs((const int4*)(row + e + 4));
            int4 c0 = __ldcs((const int4*)(col + e));
            int4 c1 = __ldcs((const int4*)(col + e + 4));
            float4 a0 = __ldcs((const float4*)(attr + e));
            float4 a1 = __ldcs((const float4*)(attr + e + 4));
            float4 v0, v1;
            v0.x = g_dinv[r0.x] * a0.x * g_diag[c0.x];
            v0.y = g_dinv[r0.y] * a0.y * g_diag[c0.y];
            v0.z = g_dinv[r0.z] * a0.z * g_diag[c0.z];
            v0.w = g_dinv[r0.w] * a0.w * g_diag[c0.w];
            v1.x = g_dinv[r1.x] * a1.x * g_diag[c1.x];
            v1.y = g_dinv[r1.y] * a1.y * g_diag[c1.y];
            v1.z = g_dinv[r1.z] * a1.z * g_diag[c1.z];
            v1.w = g_dinv[r1.w] * a1.w * g_diag[c1.w];
            __stcs((float4*)(out + e),     v0);
            __stcs((float4*)(out + e + 4), v1);
        } else {
            for (; e < E; ++e)
                out[e] = g_dinv[row[e]] * attr[e] * g_diag[col[e]];
        }
    }
}

// ---------------------------------------------------------------------------
// Hedge-path kernels (only launched for unexpected out_size layouts).
// ---------------------------------------------------------------------------
__global__ void probe_kernel(const void* __restrict__ ei, int N, int E) {
    g_is64 = probe_is64_once(ei, N, E);
}

__global__ void idx_copy_kernel(const void* __restrict__ src,
                                void* __restrict__ dst, int n2e) {
    const int is64 = g_is64;
    int i = (blockIdx.x * blockDim.x + threadIdx.x) * 4;
    if (is64) {
        const long long* s = (const long long*)src;
        long long* d = (long long*)dst;
        if (i + 4 <= n2e) {
            *(longlong2*)(d + i)     = *(const longlong2*)(s + i);
            *(longlong2*)(d + i + 2) = *(const longlong2*)(s + i + 2);
        } else {
            for (; i < n2e; ++i) d[i] = s[i];
        }
    } else {
        const int* s = (const int*)src;
        int* d = (int*)dst;
        if (i + 4 <= n2e) {
            *(int4*)(d + i) = *(const int4*)(s + i);
        } else {
            for (; i < n2e; ++i) d[i] = s[i];
        }
    }
}

extern "C" void kernel_launch(void* const* d_in, const int* in_sizes, int n_in,
                              void* d_out, int out_size) {
    const float* x    = (const float*)d_in[0];
    const void*  ei   = d_in[1];                 // [2, E] int32 or int64
    const float* attr = (const float*)d_in[2];
    const float* w    = (const float*)d_in[3];
    const float* b    = (const float*)d_in[4];

    int D = in_sizes[3];
    int N = in_sizes[0] / D;
    int E = in_sizes[2];

    const int threads = 256;

    // Indices-only layout hedge (no values) — separate simple path.
    if (out_size == 2 * E) {
        probe_kernel<<<1, 1>>>(ei, N, E);
        int n2e = 2 * E;
        int work = (n2e + 3) / 4;
        int blocks = (work + threads - 1) / threads;
        idx_copy_kernel<<<blocks, threads>>>(ei, d_out, n2e);
        return;
    }

    const bool tuple = (out_size == 3 * E);   // flattened (idx-as-float, vals)
    float* castOut = tuple ? (float*)d_out : nullptr;
    float* val_out = tuple ? (float*)d_out + 2 * E : (float*)d_out;

    // Stage 1 (3-way fused): deg + cast + diag in one interleaved grid.
    {
        int warpsPerBlock = threads / 32;                  // 8 rows per CTA
        int nDiag = (N + warpsPerBlock - 1) / warpsPerBlock;
        int perCTA = threads * 8;                          // 2048 elems/CTA
        int nDeg  = (E + perCTA - 1) / perCTA;
        int nCast = tuple ? (2 * E + perCTA - 1) / perCTA : 0;
        int total = nDiag + nDeg + nCast;
        int f = (total + nDeg - 1) / nDeg;                 // deg stride
        int grid = total + f + 2;                          // spares guarded
        int h;                                             // cast stride
        if (nCast > 0)
            h = (nDiag + nCast + nCast - 1) / nCast;
        else
            h = grid;                                      // only j=0, guarded
        fused_diag_deg_cast<<<grid, threads>>>(x, w, b, ei, castOut,
                                               N, D, E,
                                               nDiag, nDeg, nCast, f, h);
    }
    // Stage 2: invert degree + rezero g_deg (restores invariant for replay).
    {
        int work = (N + 3) / 4;
        int blocks = (work + threads - 1) / threads;
        inv_kernel<<<blocks, threads>>>(N);
    }
    // Stage 3: values.
    {
        int work = (E + 7) / 8;
        int blocks = (work + threads - 1) / threads;
        val_kernel<<<blocks, threads>>>(ei, attr, val_out, N, E);
    }
}